// round 6
// baseline (speedup 1.0000x reference)
#include <cuda_runtime.h>

#define NN 50000
#define KK 16
#define DD 256
#define LN_EPS 1e-5f

// Scratch: z[n,:] = sum_k norm_w[n,k] * features[nb[n,k],:]   (51.2 MB)
// float4 type guarantees 16B alignment for the 128-bit LDG/STG.
__device__ float4 g_z4[(size_t)NN * DD / 4];

// ---------------------------------------------------------------------------
// Kernel 1: weighted neighbor gather. One warp per node.
// Each lane owns 8 output floats (2 x float4). Loads are coalesced 128B rows.
// NOTE: neighbors arrive as int32 (JAX x64 is disabled; jnp.int64 demotes).
// ---------------------------------------------------------------------------
__global__ void __launch_bounds__(256) gather_kernel(
    const float* __restrict__ feats,
    const int*   __restrict__ nbr,
    const float* __restrict__ iw)
{
    int warp = blockIdx.x * (blockDim.x >> 5) + (threadIdx.x >> 5);
    int lane = threadIdx.x & 31;
    if (warp >= NN) return;

    float w = 0.0f;
    int idx = 0;
    if (lane < KK) {
        w   = iw[warp * KK + lane];
        idx = nbr[warp * KK + lane];
    }
    // warp-wide sum of the 16 weights (lanes >=16 contribute 0)
    float wsum = w;
    #pragma unroll
    for (int o = 16; o >= 1; o >>= 1)
        wsum += __shfl_xor_sync(0xffffffffu, wsum, o);

    float weff = (wsum == 0.0f) ? (1.0f / KK) : (w / wsum);

    float4 a0 = make_float4(0.f, 0.f, 0.f, 0.f);
    float4 a1 = make_float4(0.f, 0.f, 0.f, 0.f);

    #pragma unroll
    for (int k = 0; k < KK; k++) {
        float wk = __shfl_sync(0xffffffffu, weff, k);
        int   nk = __shfl_sync(0xffffffffu, idx,  k);
        const float4* rp = reinterpret_cast<const float4*>(feats + (size_t)nk * DD);
        float4 f0 = __ldg(rp + lane);
        float4 f1 = __ldg(rp + lane + 32);
        a0.x += wk * f0.x; a0.y += wk * f0.y; a0.z += wk * f0.z; a0.w += wk * f0.w;
        a1.x += wk * f1.x; a1.y += wk * f1.y; a1.z += wk * f1.z; a1.w += wk * f1.w;
    }

    float4* zp = g_z4 + (size_t)warp * (DD / 4);
    zp[lane]      = a0;
    zp[lane + 32] = a1;
}

// ---------------------------------------------------------------------------
// Kernel 2: out = LayerNorm(z @ W + b) * gamma + beta, fused.
// Block tile 64x256 (full output width -> LN stays in-block).
// 256 threads: warp tm owns rows tm*8..tm*8+7; lane tn owns cols tn*8..+7.
// Row LN reduction = intra-warp shuffle (each warp holds 8 complete rows).
// ---------------------------------------------------------------------------
#define BM 64
#define BN 256
#define BK 16
#define TM 8
#define TN 8

__global__ void __launch_bounds__(256, 2) gemm_ln_kernel(
    const float* __restrict__ Wm,
    const float* __restrict__ bias,
    const float* __restrict__ gamma,
    const float* __restrict__ beta,
    float* __restrict__ out)
{
    __shared__ float As[BK][BM];   // A transposed: As[k][m]
    __shared__ float Bs[BK][BN];

    const int tid = threadIdx.x;
    const int tn  = tid & 31;
    const int tm  = tid >> 5;
    const int brow = blockIdx.x * BM;

    float acc[TM][TN];
    #pragma unroll
    for (int i = 0; i < TM; i++)
        #pragma unroll
        for (int j = 0; j < TN; j++)
            acc[i][j] = 0.0f;

    const int arow = tid >> 2;
    const int aq   = tid & 3;
    const int grow = brow + arow;

    for (int k0 = 0; k0 < DD; k0 += BK) {
        // ---- load A 64x16 (transposed into As) ----
        float4 av = make_float4(0.f, 0.f, 0.f, 0.f);
        if (grow < NN)
            av = g_z4[(size_t)grow * (DD / 4) + (k0 >> 2) + aq];
        As[aq * 4 + 0][arow] = av.x;
        As[aq * 4 + 1][arow] = av.y;
        As[aq * 4 + 2][arow] = av.z;
        As[aq * 4 + 3][arow] = av.w;

        // ---- load B 16x256 ----
        #pragma unroll
        for (int i = 0; i < 4; i++) {
            int lin = tid + i * 256;
            int rk  = lin >> 6;        // 0..15
            int c4  = lin & 63;        // float4 index within row
            *reinterpret_cast<float4*>(&Bs[rk][c4 * 4]) =
                *reinterpret_cast<const float4*>(Wm + (size_t)(k0 + rk) * DD + c4 * 4);
        }
        __syncthreads();

        #pragma unroll
        for (int k = 0; k < BK; k++) {
            float a[TM], bb[TN];
            *reinterpret_cast<float4*>(&a[0])  = *reinterpret_cast<float4*>(&As[k][tm * TM]);
            *reinterpret_cast<float4*>(&a[4])  = *reinterpret_cast<float4*>(&As[k][tm * TM + 4]);
            *reinterpret_cast<float4*>(&bb[0]) = *reinterpret_cast<float4*>(&Bs[k][tn * TN]);
            *reinterpret_cast<float4*>(&bb[4]) = *reinterpret_cast<float4*>(&Bs[k][tn * TN + 4]);
            #pragma unroll
            for (int i = 0; i < TM; i++)
                #pragma unroll
                for (int j = 0; j < TN; j++)
                    acc[i][j] = fmaf(a[i], bb[j], acc[i][j]);
        }
        __syncthreads();
    }

    // ---- epilogue: +bias, LayerNorm per row (warp owns 8 full rows) ----
    float bv[TN], gv[TN], tv[TN];
    *reinterpret_cast<float4*>(&bv[0]) = *reinterpret_cast<const float4*>(bias  + tn * TN);
    *reinterpret_cast<float4*>(&bv[4]) = *reinterpret_cast<const float4*>(bias  + tn * TN + 4);
    *reinterpret_cast<float4*>(&gv[0]) = *reinterpret_cast<const float4*>(gamma + tn * TN);
    *reinterpret_cast<float4*>(&gv[4]) = *reinterpret_cast<const float4*>(gamma + tn * TN + 4);
    *reinterpret_cast<float4*>(&tv[0]) = *reinterpret_cast<const float4*>(beta  + tn * TN);
    *reinterpret_cast<float4*>(&tv[4]) = *reinterpret_cast<const float4*>(beta  + tn * TN + 4);

    #pragma unroll
    for (int i = 0; i < TM; i++) {
        float v[TN];
        float s = 0.f, s2 = 0.f;
        #pragma unroll
        for (int j = 0; j < TN; j++) {
            v[j] = acc[i][j] + bv[j];
            s  += v[j];
            s2 += v[j] * v[j];
        }
        #pragma unroll
        for (int o = 16; o >= 1; o >>= 1) {
            s  += __shfl_xor_sync(0xffffffffu, s,  o);
            s2 += __shfl_xor_sync(0xffffffffu, s2, o);
        }
        float mean = s * (1.0f / BN);
        float var  = s2 * (1.0f / BN) - mean * mean;
        float rstd = rsqrtf(var + LN_EPS);

        int row = brow + tm * TM + i;
        if (row < NN) {
            float o8[TN];
            #pragma unroll
            for (int j = 0; j < TN; j++)
                o8[j] = (v[j] - mean) * rstd * gv[j] + tv[j];
            float* op = out + (size_t)row * DD + tn * TN;
            *reinterpret_cast<float4*>(op)     = *reinterpret_cast<float4*>(&o8[0]);
            *reinterpret_cast<float4*>(op + 4) = *reinterpret_cast<float4*>(&o8[4]);
        }
    }
}

// ---------------------------------------------------------------------------
extern "C" void kernel_launch(void* const* d_in, const int* in_sizes, int n_in,
                              void* d_out, int out_size)
{
    const float* feats = (const float*)d_in[0];
    const int*   nbr   = (const int*)d_in[1];    // int32! (JAX x64 disabled)
    const float* iw    = (const float*)d_in[2];
    const float* Wm    = (const float*)d_in[3];
    const float* bias  = (const float*)d_in[4];
    const float* gamma = (const float*)d_in[5];
    const float* beta  = (const float*)d_in[6];
    float*       out   = (float*)d_out;

    // 8 warps/block, 1 warp per node: 6250 * 8 = 50000 exactly
    gather_kernel<<<6250, 256>>>(feats, nbr, iw);

    gemm_ln_kernel<<<(NN + BM - 1) / BM, 256>>>(Wm, bias, gamma, beta, out);
}

// round 8
// speedup vs baseline: 1.5722x; 1.5722x over previous
#include <cuda_runtime.h>
#include <cuda_bf16.h>
#include <cstdint>

#define NN 50000
#define KK 16
#define DD 256
#define LN_EPS 1e-5f

#define NTILES 391          // ceil(50000/128)
#define NPAD   (NTILES*128) // 50048

// ---------------- device scratch (zero-initialized at load) ----------------
// z split into bf16 hi/lo, [NPAD][256] bf16 each => 32 uint4 per row
__device__ uint4 g_ah[(size_t)NPAD * 32];
__device__ uint4 g_al[(size_t)NPAD * 32];
// W^T split: [n=256][k=256] bf16 => 32 uint4 per row (row.col B operand)
__device__ uint4 g_wh[(size_t)256 * 32];
__device__ uint4 g_wl[(size_t)256 * 32];

#define SWZ(off) ((off) ^ (((off) >> 3) & 0x70))

__device__ __forceinline__ uint32_t smem_to_u32(const void* p) {
    uint32_t a;
    asm("{ .reg .u64 t; cvta.to.shared.u64 t, %1; cvt.u32.u64 %0, t; }" : "=r"(a) : "l"(p));
    return a;
}
__device__ __forceinline__ void ldsm_x4(uint32_t addr, uint32_t* r) {
    asm volatile("ldmatrix.sync.aligned.m8n8.x4.shared.b16 {%0,%1,%2,%3}, [%4];"
                 : "=r"(r[0]), "=r"(r[1]), "=r"(r[2]), "=r"(r[3]) : "r"(addr));
}
__device__ __forceinline__ void mma16816(float* c, const uint32_t* a, uint32_t b0, uint32_t b1) {
    asm volatile("mma.sync.aligned.m16n8k16.row.col.f32.bf16.bf16.f32 "
                 "{%0,%1,%2,%3}, {%4,%5,%6,%7}, {%8,%9}, {%0,%1,%2,%3};"
                 : "+f"(c[0]), "+f"(c[1]), "+f"(c[2]), "+f"(c[3])
                 : "r"(a[0]), "r"(a[1]), "r"(a[2]), "r"(a[3]), "r"(b0), "r"(b1));
}

__device__ __forceinline__ void split2(float v0, float v1, unsigned& hi, unsigned& lo) {
    __nv_bfloat16 h0 = __float2bfloat16_rn(v0);
    __nv_bfloat16 h1 = __float2bfloat16_rn(v1);
    __nv_bfloat16 l0 = __float2bfloat16_rn(v0 - __bfloat162float(h0));
    __nv_bfloat16 l1 = __float2bfloat16_rn(v1 - __bfloat162float(h1));
    hi = ((unsigned)__bfloat16_as_ushort(h1) << 16) | (unsigned)__bfloat16_as_ushort(h0);
    lo = ((unsigned)__bfloat16_as_ushort(l1) << 16) | (unsigned)__bfloat16_as_ushort(l0);
}

// ---------------------------------------------------------------------------
// Kernel 1: weighted neighbor gather -> z, emitted as split bf16 hi/lo.
// One warp per node; coalesced 128B row loads. neighbors are int32.
// ---------------------------------------------------------------------------
__global__ void __launch_bounds__(256) gather_kernel(
    const float* __restrict__ feats,
    const int*   __restrict__ nbr,
    const float* __restrict__ iw)
{
    int warp = blockIdx.x * (blockDim.x >> 5) + (threadIdx.x >> 5);
    int lane = threadIdx.x & 31;
    if (warp >= NN) return;

    float w = 0.0f;
    int idx = 0;
    if (lane < KK) {
        w   = iw[warp * KK + lane];
        idx = nbr[warp * KK + lane];
    }
    float wsum = w;
    #pragma unroll
    for (int o = 16; o >= 1; o >>= 1)
        wsum += __shfl_xor_sync(0xffffffffu, wsum, o);
    float weff = (wsum == 0.0f) ? (1.0f / KK) : (w / wsum);

    float4 a0 = make_float4(0.f, 0.f, 0.f, 0.f);
    float4 a1 = make_float4(0.f, 0.f, 0.f, 0.f);

    #pragma unroll
    for (int k = 0; k < KK; k++) {
        float wk = __shfl_sync(0xffffffffu, weff, k);
        int   nk = __shfl_sync(0xffffffffu, idx,  k);
        const float4* rp = reinterpret_cast<const float4*>(feats + (size_t)nk * DD);
        float4 f0 = __ldg(rp + lane);
        float4 f1 = __ldg(rp + lane + 32);
        a0.x += wk * f0.x; a0.y += wk * f0.y; a0.z += wk * f0.z; a0.w += wk * f0.w;
        a1.x += wk * f1.x; a1.y += wk * f1.y; a1.z += wk * f1.z; a1.w += wk * f1.w;
    }

    uint2* ah = reinterpret_cast<uint2*>(g_ah) + (size_t)warp * 64;
    uint2* al = reinterpret_cast<uint2*>(g_al) + (size_t)warp * 64;
    uint2 h, l;
    split2(a0.x, a0.y, h.x, l.x); split2(a0.z, a0.w, h.y, l.y);
    ah[lane] = h;  al[lane] = l;
    split2(a1.x, a1.y, h.x, l.x); split2(a1.z, a1.w, h.y, l.y);
    ah[32 + lane] = h;  al[32 + lane] = l;
}

// ---------------------------------------------------------------------------
// Kernel 1b: split + transpose W [k][n] fp32 -> g_wh/g_wl [n][k] bf16
// ---------------------------------------------------------------------------
__global__ void __launch_bounds__(256) wprep_kernel(const float* __restrict__ W)
{
    int idx = blockIdx.x * 256 + threadIdx.x;   // idx = n*256 + k
    int n = idx >> 8, k = idx & 255;
    float v = W[(size_t)k * 256 + n];
    __nv_bfloat16 h = __float2bfloat16_rn(v);
    __nv_bfloat16 l = __float2bfloat16_rn(v - __bfloat162float(h));
    reinterpret_cast<unsigned short*>(g_wh)[idx] = __bfloat16_as_ushort(h);
    reinterpret_cast<unsigned short*>(g_wl)[idx] = __bfloat16_as_ushort(l);
}

// ---------------------------------------------------------------------------
// Kernel 2: HMMA (mma.sync bf16) GEMM, 3-term split, fused LayerNorm.
// Block 128x256 (full width), 512 threads = 4(m) x 4(n) warps, warp tile 32x64.
// K chunks of 64 staged in swizzled smem; ldmatrix feeds mma.sync.
// ---------------------------------------------------------------------------
#define SMO_AH 0
#define SMO_AL 16384
#define SMO_BH 32768
#define SMO_BL 65536
#define SMO_CONST 98304                 // bias/gamma/beta: 3 x 1KB
#define SMEM_TOTAL (SMO_CONST + 3072)   // 101376 B
// epilogue overlays (after mainloop): psum float2[4][128] @0, stats float2[128] @4096

__global__ void __launch_bounds__(512) gemm_tc_kernel(
    const float* __restrict__ bias,
    const float* __restrict__ gamma,
    const float* __restrict__ beta,
    float* __restrict__ out)
{
    extern __shared__ char smem[];
    const uint32_t sb = smem_to_u32(smem);
    const int tid  = threadIdx.x;
    const int wid  = tid >> 5;
    const int lane = tid & 31;
    const int wm   = wid >> 2;          // 0..3 (m)
    const int wn   = wid & 3;           // 0..3 (n)
    const int row0 = blockIdx.x * 128;

    float* sC = reinterpret_cast<float*>(smem + SMO_CONST);
    if (tid < 256) {
        sC[tid]       = bias[tid];
        sC[256 + tid] = gamma[tid];
        sC[512 + tid] = beta[tid];
    }

    float c[2][8][4];
    #pragma unroll
    for (int i = 0; i < 2; i++)
        #pragma unroll
        for (int j = 0; j < 8; j++)
            #pragma unroll
            for (int q = 0; q < 4; q++) c[i][j][q] = 0.f;

    // ldmatrix per-lane addresses (row within 16-row tile, 16B k-half)
    const int lrow = lane & 15;
    const int lkb  = (lane >> 4) * 16;

    for (int ch = 0; ch < 4; ch++) {
        __syncthreads();
        // ---- A tiles: 128 rows x 64 bf16 (hi & lo), 1024 uint4 each ----
        #pragma unroll
        for (int i = 0; i < 2; i++) {
            int e = tid + i * 512;
            int r = e >> 3, q = e & 7;
            uint32_t so = SWZ((uint32_t)(r * 128 + q * 16));
            size_t gi = (size_t)(row0 + r) * 32 + ch * 8 + q;
            *reinterpret_cast<uint4*>(smem + SMO_AH + so) = g_ah[gi];
            *reinterpret_cast<uint4*>(smem + SMO_AL + so) = g_al[gi];
        }
        // ---- B tiles: 256 rows x 64 bf16 (hi & lo), 2048 uint4 each ----
        #pragma unroll
        for (int i = 0; i < 4; i++) {
            int e = tid + i * 512;
            int r = e >> 3, q = e & 7;
            uint32_t so = SWZ((uint32_t)(r * 128 + q * 16));
            size_t gi = (size_t)r * 32 + ch * 8 + q;
            *reinterpret_cast<uint4*>(smem + SMO_BH + so) = g_wh[gi];
            *reinterpret_cast<uint4*>(smem + SMO_BL + so) = g_wl[gi];
        }
        __syncthreads();

        #pragma unroll
        for (int ks = 0; ks < 4; ks++) {
            const int kb = ks * 32 + lkb;
            uint32_t ah[2][4], al[2][4];
            #pragma unroll
            for (int mm = 0; mm < 2; mm++) {
                uint32_t off = SWZ((uint32_t)((wm * 32 + mm * 16 + lrow) * 128 + kb));
                ldsm_x4(sb + SMO_AH + off, ah[mm]);
                ldsm_x4(sb + SMO_AL + off, al[mm]);
            }
            #pragma unroll
            for (int np = 0; np < 4; np++) {
                uint32_t off = SWZ((uint32_t)((wn * 64 + np * 16 + lrow) * 128 + kb));
                uint32_t bh[4], bl[4];
                ldsm_x4(sb + SMO_BH + off, bh);
                ldsm_x4(sb + SMO_BL + off, bl);
                #pragma unroll
                for (int sub = 0; sub < 2; sub++) {
                    int mn = np * 2 + sub;
                    #pragma unroll
                    for (int mm = 0; mm < 2; mm++) {
                        mma16816(c[mm][mn], ah[mm], bh[sub], bh[2 + sub]); // hi*hi
                        mma16816(c[mm][mn], ah[mm], bl[sub], bl[2 + sub]); // hi*lo
                        mma16816(c[mm][mn], al[mm], bh[sub], bh[2 + sub]); // lo*hi
                    }
                }
            }
        }
    }
    __syncthreads();   // tiles dead; smem reused for LN reductions

    // ---- +bias, per-lane partial row sums ----
    const int q2 = 2 * (lane & 3);
    #pragma unroll
    for (int mm = 0; mm < 2; mm++)
        #pragma unroll
        for (int mn = 0; mn < 8; mn++) {
            int col = wn * 64 + mn * 8 + q2;
            float b0 = sC[col], b1 = sC[col + 1];
            c[mm][mn][0] += b0; c[mm][mn][1] += b1;
            c[mm][mn][2] += b0; c[mm][mn][3] += b1;
        }

    float2* psum  = reinterpret_cast<float2*>(smem);          // [wn*128 + row]
    float2* stats = reinterpret_cast<float2*>(smem + 4096);   // [row]

    #pragma unroll
    for (int mm = 0; mm < 2; mm++) {
        #pragma unroll
        for (int h = 0; h < 2; h++) {
            float s = 0.f, s2 = 0.f;
            #pragma unroll
            for (int mn = 0; mn < 8; mn++) {
                float v0 = c[mm][mn][h * 2 + 0];
                float v1 = c[mm][mn][h * 2 + 1];
                s += v0 + v1;  s2 += v0 * v0 + v1 * v1;
            }
            // combine across the 4 lanes of this row (quad)
            s  += __shfl_xor_sync(0xffffffffu, s, 1);
            s  += __shfl_xor_sync(0xffffffffu, s, 2);
            s2 += __shfl_xor_sync(0xffffffffu, s2, 1);
            s2 += __shfl_xor_sync(0xffffffffu, s2, 2);
            if ((lane & 3) == 0) {
                int row = wm * 32 + mm * 16 + h * 8 + (lane >> 2);
                psum[wn * 128 + row] = make_float2(s, s2);
            }
        }
    }
    __syncthreads();

    if (tid < 128) {
        float s = 0.f, s2 = 0.f;
        #pragma unroll
        for (int p = 0; p < 4; p++) {
            float2 v = psum[p * 128 + tid];
            s += v.x;  s2 += v.y;
        }
        float mean = s * (1.0f / 256.0f);
        float var  = s2 * (1.0f / 256.0f) - mean * mean;
        stats[tid] = make_float2(mean, rsqrtf(var + LN_EPS));
    }
    __syncthreads();

    // ---- normalize + store ----
    #pragma unroll
    for (int mm = 0; mm < 2; mm++)
        #pragma unroll
        for (int h = 0; h < 2; h++) {
            int row  = wm * 32 + mm * 16 + h * 8 + (lane >> 2);
            int grow = row0 + row;
            if (grow >= NN) continue;
            float2 st = stats[row];
            #pragma unroll
            for (int mn = 0; mn < 8; mn++) {
                int col = wn * 64 + mn * 8 + q2;
                float v0 = (c[mm][mn][h * 2 + 0] - st.x) * st.y * sC[256 + col]     + sC[512 + col];
                float v1 = (c[mm][mn][h * 2 + 1] - st.x) * st.y * sC[256 + col + 1] + sC[512 + col + 1];
                *reinterpret_cast<float2*>(out + (size_t)grow * DD + col) = make_float2(v0, v1);
            }
        }
}

// ---------------------------------------------------------------------------
extern "C" void kernel_launch(void* const* d_in, const int* in_sizes, int n_in,
                              void* d_out, int out_size)
{
    const float* feats = (const float*)d_in[0];
    const int*   nbr   = (const int*)d_in[1];    // int32 (JAX x64 disabled)
    const float* iw    = (const float*)d_in[2];
    const float* Wm    = (const float*)d_in[3];
    const float* bias  = (const float*)d_in[4];
    const float* gamma = (const float*)d_in[5];
    const float* beta  = (const float*)d_in[6];
    float*       out   = (float*)d_out;

    cudaFuncSetAttribute(gemm_tc_kernel,
                         cudaFuncAttributeMaxDynamicSharedMemorySize, SMEM_TOTAL);

    wprep_kernel<<<256, 256>>>(Wm);
    gather_kernel<<<6250, 256>>>(feats, nbr, iw);
    gemm_tc_kernel<<<NTILES, 512, SMEM_TOTAL>>>(bias, gamma, beta, out);
}